// round 4
// baseline (speedup 1.0000x reference)
#include <cuda_runtime.h>
#include <cuda_fp16.h>

// Problem constants
#define BB   32
#define NN   4096
#define CIN  32
#define COUT 64
#define KDEG 5
#define PP   4
#define NNZ_ 65536
#define ROWW (CIN*BB)          // 1024 cols total
#define NF   (KDEG*CIN)        // 160 features
#define CHUNK 8                // cols per fused-SPMM block
#define NCHUNK (ROWW/CHUNK)    // 128 blocks

// Scratch (device globals — allocation-free rule)
// chunk-major fp16 Chebyshev terms: g2[k][chunk][node][8]
__device__ __half   g2[(size_t)KDEG*NCHUNK*NN*CHUNK];
__device__ int      g_count[NN];
__device__ int      g_rowptr[NN+1];
__device__ int      g_fill[NN];
__device__ unsigned g_epack[NNZ_];    // (col:16 | half(val):16)

__device__ __forceinline__ size_t g2_base(int k, int ch) {
    return ((size_t)k*NCHUNK + ch)*(size_t)NN*CHUNK;
}

// ---------------------------------------------------------------------------
// 1) transpose x[b][n][c] -> g2[0][chunk][n][8], zero g_count
// ---------------------------------------------------------------------------
__global__ void k_transpose(const float* __restrict__ x) {
    __shared__ float t[32][33];
    int n = blockIdx.x;
    int tx = threadIdx.x;   // c on read
    int ty = threadIdx.y;   // b on read
    if (tx == 0 && ty == 0) g_count[n] = 0;
    t[ty][tx] = x[(size_t)ty * (NN*CIN) + n*CIN + tx];
    __syncthreads();
    int tid = ty*32 + tx;
    if (tid < NCHUNK) {       // chunk = c*4 + b0/8 == tid
        int c  = tid >> 2;
        int b0 = (tid & 3) * 8;
        __half2 h[4];
        #pragma unroll
        for (int j = 0; j < 4; j++)
            h[j] = __floats2half2_rn(t[b0+2*j][c], t[b0+2*j+1][c]);
        *reinterpret_cast<uint4*>(&g2[g2_base(0, tid) + (size_t)n*CHUNK]) =
            *reinterpret_cast<uint4*>(h);
    }
}

// ---------------------------------------------------------------------------
// 2) CSR build (packed 4B edges)
// ---------------------------------------------------------------------------
__global__ void k_count(const int* __restrict__ erow) {
    int i = blockIdx.x * blockDim.x + threadIdx.x;
    if (i < NNZ_) atomicAdd(&g_count[erow[i]], 1);
}

__global__ void k_scan() {   // 1 block, 1024 threads, 4 counts each
    __shared__ int wsum[32];
    int t = threadIdx.x;
    int lane = t & 31, wid = t >> 5;
    int c0 = g_count[t*4+0], c1 = g_count[t*4+1],
        c2 = g_count[t*4+2], c3 = g_count[t*4+3];
    int sum = c0 + c1 + c2 + c3;
    int incl = sum;
    #pragma unroll
    for (int off = 1; off < 32; off <<= 1) {
        int v = __shfl_up_sync(0xffffffffu, incl, off);
        if (lane >= off) incl += v;
    }
    if (lane == 31) wsum[wid] = incl;
    __syncthreads();
    if (wid == 0) {
        int w = wsum[lane];
        int wi = w;
        #pragma unroll
        for (int off = 1; off < 32; off <<= 1) {
            int v = __shfl_up_sync(0xffffffffu, wi, off);
            if (lane >= off) wi += v;
        }
        wsum[lane] = wi - w;
    }
    __syncthreads();
    int run = wsum[wid] + incl - sum;
    g_rowptr[t*4+0] = run; g_fill[t*4+0] = run; run += c0;
    g_rowptr[t*4+1] = run; g_fill[t*4+1] = run; run += c1;
    g_rowptr[t*4+2] = run; g_fill[t*4+2] = run; run += c2;
    g_rowptr[t*4+3] = run; g_fill[t*4+3] = run; run += c3;
    if (t == 1023) g_rowptr[NN] = run;
}

__global__ void k_scatter(const int* __restrict__ erow,
                          const int* __restrict__ ecol,
                          const float* __restrict__ eval) {
    int i = blockIdx.x * blockDim.x + threadIdx.x;
    if (i < NNZ_) {
        int r = erow[i];
        int pos = atomicAdd(&g_fill[r], 1);
        unsigned hv = __half_as_ushort(__float2half(eval[i]));
        g_epack[pos] = (unsigned)ecol[i] | (hv << 16);
    }
}

// ---------------------------------------------------------------------------
// 3) Fused Chebyshev recursion: one block per 8-column chunk, all 4 levels
//    block-local. Gathers read SMEM (64KB level buffer), not L2.
//    Layout: buf ping-pong; x_k overwrites x_{k-2} after own correction read.
//    lane = r4*8 + e8 : 4 rows per warp, 8 edge-lanes per row.
// ---------------------------------------------------------------------------
#define CHEB_TPB 1024
#define SMEM_CHEB (2*NN*CHUNK*2 + (NN+1)*4)   // 2 bufs + rowptr = 147460 B

__global__ void __launch_bounds__(CHEB_TPB) k_cheb() {
    extern __shared__ __align__(16) char sm[];
    __half* buf0 = reinterpret_cast<__half*>(sm);
    __half* buf1 = reinterpret_cast<__half*>(sm + NN*CHUNK*2);
    int*    srp  = reinterpret_cast<int*>(sm + 2*NN*CHUNK*2);

    int ch = blockIdx.x;
    int t  = threadIdx.x;
    // stage rowptr
    for (int i = t; i <= NN; i += CHEB_TPB) srp[i] = g_rowptr[i];
    // stage x0 chunk (coalesced uint4)
    {
        const uint4* src = reinterpret_cast<const uint4*>(&g2[g2_base(0, ch)]);
        uint4* dst = reinterpret_cast<uint4*>(buf0);
        for (int n = t; n < NN; n += CHEB_TPB) dst[n] = src[n];
    }
    __syncthreads();

    int w    = t >> 5;
    int lane = t & 31;
    int r4   = lane >> 3;
    int e8   = lane & 7;

    #pragma unroll
    for (int k = 1; k < KDEG; k++) {
        __half* bp = (k & 1) ? buf0 : buf1;   // x_{k-1}
        __half* bn = (k & 1) ? buf1 : buf0;   // holds x_{k-2}, gets x_k
        for (int it = 0; it < NN/128; it++) {
            int n = it*128 + w*4 + r4;
            int s = srp[n], e = srp[n+1];
            float a0=0.f,a1=0.f,a2=0.f,a3=0.f,a4=0.f,a5=0.f,a6=0.f,a7=0.f;
            for (int p = s + e8; p < e; p += 8) {
                unsigned u = g_epack[p];
                int col = u & 0xFFFF;
                float v = __half2float(__ushort_as_half((unsigned short)(u >> 16)));
                uint4 xv = *reinterpret_cast<const uint4*>(bp + col*CHUNK);
                __half2* hp = reinterpret_cast<__half2*>(&xv);
                float2 f0 = __half22float2(hp[0]);
                float2 f1 = __half22float2(hp[1]);
                float2 f2 = __half22float2(hp[2]);
                float2 f3 = __half22float2(hp[3]);
                a0 = fmaf(v, f0.x, a0); a1 = fmaf(v, f0.y, a1);
                a2 = fmaf(v, f1.x, a2); a3 = fmaf(v, f1.y, a3);
                a4 = fmaf(v, f2.x, a4); a5 = fmaf(v, f2.y, a5);
                a6 = fmaf(v, f3.x, a6); a7 = fmaf(v, f3.y, a7);
            }
            #pragma unroll
            for (int m = 1; m < 8; m <<= 1) {
                a0 += __shfl_xor_sync(0xffffffffu, a0, m);
                a1 += __shfl_xor_sync(0xffffffffu, a1, m);
                a2 += __shfl_xor_sync(0xffffffffu, a2, m);
                a3 += __shfl_xor_sync(0xffffffffu, a3, m);
                a4 += __shfl_xor_sync(0xffffffffu, a4, m);
                a5 += __shfl_xor_sync(0xffffffffu, a5, m);
                a6 += __shfl_xor_sync(0xffffffffu, a6, m);
                a7 += __shfl_xor_sync(0xffffffffu, a7, m);
            }
            if (e8 == 0) {
                float r0,r1,r2,r3,r4_,r5,r6,r7;
                if (k > 1) {
                    uint4 old = *reinterpret_cast<const uint4*>(bn + n*CHUNK);
                    __half2* op = reinterpret_cast<__half2*>(&old);
                    float2 o0 = __half22float2(op[0]);
                    float2 o1 = __half22float2(op[1]);
                    float2 o2 = __half22float2(op[2]);
                    float2 o3 = __half22float2(op[3]);
                    r0 = 2.f*a0 - o0.x; r1 = 2.f*a1 - o0.y;
                    r2 = 2.f*a2 - o1.x; r3 = 2.f*a3 - o1.y;
                    r4_ = 2.f*a4 - o2.x; r5 = 2.f*a5 - o2.y;
                    r6 = 2.f*a6 - o3.x; r7 = 2.f*a7 - o3.y;
                } else {
                    r0=a0; r1=a1; r2=a2; r3=a3; r4_=a4; r5=a5; r6=a6; r7=a7;
                }
                __half2 h[4];
                h[0] = __floats2half2_rn(r0, r1);
                h[1] = __floats2half2_rn(r2, r3);
                h[2] = __floats2half2_rn(r4_, r5);
                h[3] = __floats2half2_rn(r6, r7);
                *reinterpret_cast<uint4*>(bn + n*CHUNK) =
                    *reinterpret_cast<uint4*>(h);
            }
        }
        __syncthreads();
        // coalesced write-out of level k (safe to overlap with next level:
        // next level writes the OTHER buffer)
        uint4* dst = reinterpret_cast<uint4*>(&g2[g2_base(k, ch)]);
        const uint4* src = reinterpret_cast<const uint4*>(bn);
        for (int n2 = t; n2 < NN; n2 += CHEB_TPB) dst[n2] = src[n2];
    }
}

// ---------------------------------------------------------------------------
// 4) Tensor-core GEMM + bias + ReLU + maxpool(P=4)  (reads g2 chunk layout)
// ---------------------------------------------------------------------------
#define A_STRIDE 136
#define W_STRIDE 72

__device__ __forceinline__ void ldsm_x4_trans(unsigned& r0, unsigned& r1,
                                              unsigned& r2, unsigned& r3,
                                              unsigned addr) {
    asm volatile("ldmatrix.sync.aligned.m8n8.x4.trans.shared.b16 {%0,%1,%2,%3}, [%4];\n"
                 : "=r"(r0), "=r"(r1), "=r"(r2), "=r"(r3) : "r"(addr));
}

__device__ __forceinline__ void mma16816(float* d, unsigned a0, unsigned a1,
                                         unsigned a2, unsigned a3,
                                         unsigned b0, unsigned b1) {
    asm volatile("mma.sync.aligned.m16n8k16.row.col.f32.f16.f16.f32 "
                 "{%0,%1,%2,%3}, {%4,%5,%6,%7}, {%8,%9}, {%0,%1,%2,%3};\n"
                 : "+f"(d[0]), "+f"(d[1]), "+f"(d[2]), "+f"(d[3])
                 : "r"(a0), "r"(a1), "r"(a2), "r"(a3), "r"(b0), "r"(b1));
}

__global__ void __launch_bounds__(128) k_gemm(const float* __restrict__ W,
                                              const float* __restrict__ bias,
                                              float* __restrict__ out) {
    __shared__ __align__(16) char buf[80*A_STRIDE*2 + NF*W_STRIDE*2];
    __half* aS = reinterpret_cast<__half*>(buf);
    __half* wS = reinterpret_cast<__half*>(buf + 80*A_STRIDE*2);
    float*  red = reinterpret_cast<float*>(buf);

    int g  = blockIdx.x;
    int n0 = g * PP;
    int t  = threadIdx.x;
    int w  = t >> 5;
    int lane = t & 31;

    unsigned aS_base = (unsigned)__cvta_generic_to_shared(aS);
    unsigned wS_base = (unsigned)__cvta_generic_to_shared(wS);

    float acc[2][8][4];
    #pragma unroll
    for (int mt = 0; mt < 2; mt++)
        #pragma unroll
        for (int nt = 0; nt < 8; nt++)
            #pragma unroll
            for (int d = 0; d < 4; d++) acc[mt][nt][d] = 0.f;

    #pragma unroll
    for (int it = 0; it < 20; it++) {
        int chn = it*128 + t;
        int f  = chn >> 4;
        int o4 = (chn & 15) * 4;
        float4 wv = *reinterpret_cast<const float4*>(W + f*COUT + o4);
        __half2 h0 = __floats2half2_rn(wv.x, wv.y);
        __half2 h1 = __floats2half2_rn(wv.z, wv.w);
        uint2 hu;
        hu.x = *reinterpret_cast<unsigned*>(&h0);
        hu.y = *reinterpret_cast<unsigned*>(&h1);
        *reinterpret_cast<uint2*>(wS + f*W_STRIDE + o4) = hu;
    }

    for (int f0 = 0; f0 < NF; f0 += 80) {
        #pragma unroll
        for (int it = 0; it < 10; it++) {
            int chn = it*128 + t;
            int lf = chn >> 4;
            int rc = chn & 15;
            int p  = rc >> 2;
            int bq = rc & 3;          // b0/8
            int f  = f0 + lf;
            int c  = f / KDEG;
            int k  = f - KDEG*c;
            uint4 v = *reinterpret_cast<const uint4*>(
                &g2[g2_base(k, c*4 + bq) + (size_t)(n0 + p)*CHUNK]);
            *reinterpret_cast<uint4*>(aS + lf*A_STRIDE + p*32 + bq*8) = v;
        }
        __syncthreads();

        #pragma unroll
        for (int kc = 0; kc < 5; kc++) {
            int lf0 = kc * 16;
            int fg  = f0 + lf0;
            int grp = lane >> 3, lrow = lane & 7;
            int a_f = lf0 + ((grp == 2 || grp == 3) ? 8 : 0) + lrow;
            int a_c = ((grp == 1 || grp == 3) ? 8 : 0);
            unsigned a0r, a1r, a2r, a3r, a4r, a5r, a6r, a7r;
            {
                unsigned addr0 = aS_base + (a_f*A_STRIDE + w*32 + 0*16 + a_c) * 2;
                ldsm_x4_trans(a0r, a1r, a2r, a3r, addr0);
                unsigned addr1 = aS_base + (a_f*A_STRIDE + w*32 + 1*16 + a_c) * 2;
                ldsm_x4_trans(a4r, a5r, a6r, a7r, addr1);
            }
            int b_f = fg + ((grp == 1 || grp == 3) ? 8 : 0) + lrow;
            int b_n = ((grp == 2 || grp == 3) ? 8 : 0);
            #pragma unroll
            for (int ntp = 0; ntp < 4; ntp++) {
                unsigned b0r, b1r, b2r, b3r;
                unsigned addr = wS_base + (b_f*W_STRIDE + ntp*16 + b_n) * 2;
                ldsm_x4_trans(b0r, b1r, b2r, b3r, addr);
                mma16816(acc[0][ntp*2+0], a0r, a1r, a2r, a3r, b0r, b1r);
                mma16816(acc[0][ntp*2+1], a0r, a1r, a2r, a3r, b2r, b3r);
                mma16816(acc[1][ntp*2+0], a4r, a5r, a6r, a7r, b0r, b1r);
                mma16816(acc[1][ntp*2+1], a4r, a5r, a6r, a7r, b2r, b3r);
            }
        }
        __syncthreads();
    }

    #pragma unroll
    for (int mt = 0; mt < 2; mt++) {
        int r1 = mt*16 + (lane >> 2);
        #pragma unroll
        for (int nt = 0; nt < 8; nt++) {
            int c = nt*8 + (lane & 3)*2;
            red[(w*32 + r1)*64 + c]     = acc[mt][nt][0];
            red[(w*32 + r1)*64 + c + 1] = acc[mt][nt][1];
            red[(w*32 + r1 + 8)*64 + c]     = acc[mt][nt][2];
            red[(w*32 + r1 + 8)*64 + c + 1] = acc[mt][nt][3];
        }
    }
    __syncthreads();

    #pragma unroll
    for (int it = 0; it < 16; it++) {
        int idx = it*128 + t;
        int b = idx >> 6;
        int o = idx & 63;
        float bo = bias[o];
        float m = 0.f;
        #pragma unroll
        for (int p = 0; p < 4; p++)
            m = fmaxf(m, red[(p*32 + b)*64 + o] + bo);
        out[(size_t)b*((NN/PP)*COUT) + (size_t)g*COUT + o] = m;
    }
}

// ---------------------------------------------------------------------------
extern "C" void kernel_launch(void* const* d_in, const int* in_sizes, int n_in,
                              void* d_out, int out_size) {
    const float* x        = (const float*)d_in[0];
    const float* edge_val = (const float*)d_in[1];
    const float* weight   = (const float*)d_in[2];
    const float* bias     = (const float*)d_in[3];
    const int*   edge_row = (const int*)d_in[4];
    const int*   edge_col = (const int*)d_in[5];
    float* out = (float*)d_out;

    cudaFuncSetAttribute(k_cheb, cudaFuncAttributeMaxDynamicSharedMemorySize,
                         SMEM_CHEB);

    k_transpose<<<NN, dim3(32, 32)>>>(x);
    k_count<<<(NNZ_ + 255)/256, 256>>>(edge_row);
    k_scan<<<1, 1024>>>();
    k_scatter<<<(NNZ_ + 255)/256, 256>>>(edge_row, edge_col, edge_val);
    k_cheb<<<NCHUNK, CHEB_TPB, SMEM_CHEB>>>();
    k_gemm<<<NN/PP, 128>>>(weight, bias, out);
}

// round 5
// speedup vs baseline: 2.0307x; 2.0307x over previous
#include <cuda_runtime.h>
#include <cuda_fp16.h>

// Problem constants
#define BB   32
#define NN   4096
#define CIN  32
#define COUT 64
#define KDEG 5
#define PP   4
#define NNZ_ 65536
#define ROWW (CIN*BB)          // 1024 elems per node-row
#define NF   (KDEG*CIN)        // 160 features

// Scratch (device globals — allocation-free rule)
__device__ __half g_xh[KDEG][NN*ROWW];   // fp16 Chebyshev terms
__device__ int    g_count[NN];           // zero-initialized; re-zeroed by k_scan
__device__ int    g_rowptr[NN+1];
__device__ int    g_fill[NN];
__device__ int    g_ccol[NNZ_];
__device__ float  g_cval[NNZ_];

// ---------------------------------------------------------------------------
// 1) transpose x[b][n][c] -> x0[n][c*32+b] (fp16) + fused edge counting
//    (16 edges per block; g_count starts zero: init on load, re-zeroed by scan)
// ---------------------------------------------------------------------------
__global__ void k_tc(const float* __restrict__ x, const int* __restrict__ erow) {
    __shared__ float t[32][33];
    int n = blockIdx.x;
    int tx = threadIdx.x;
    int ty = threadIdx.y;
    int tid = ty*32 + tx;
    if (tid < 16) atomicAdd(&g_count[erow[n*16 + tid]], 1);
    t[ty][tx] = x[(size_t)ty * (NN*CIN) + n*CIN + tx];
    __syncthreads();
    g_xh[0][(size_t)n*ROWW + ty*32 + tx] = __float2half(t[tx][ty]);
}

// ---------------------------------------------------------------------------
// 2) CSR build
// ---------------------------------------------------------------------------
__global__ void k_scan() {   // 1 block, 1024 threads, 4 counts each
    __shared__ int wsum[32];
    int t = threadIdx.x;
    int lane = t & 31, wid = t >> 5;
    int c0 = g_count[t*4+0], c1 = g_count[t*4+1],
        c2 = g_count[t*4+2], c3 = g_count[t*4+3];
    // re-zero for the next graph replay
    g_count[t*4+0] = 0; g_count[t*4+1] = 0;
    g_count[t*4+2] = 0; g_count[t*4+3] = 0;
    int sum = c0 + c1 + c2 + c3;
    int incl = sum;
    #pragma unroll
    for (int off = 1; off < 32; off <<= 1) {
        int v = __shfl_up_sync(0xffffffffu, incl, off);
        if (lane >= off) incl += v;
    }
    if (lane == 31) wsum[wid] = incl;
    __syncthreads();
    if (wid == 0) {
        int w = wsum[lane];
        int wi = w;
        #pragma unroll
        for (int off = 1; off < 32; off <<= 1) {
            int v = __shfl_up_sync(0xffffffffu, wi, off);
            if (lane >= off) wi += v;
        }
        wsum[lane] = wi - w;
    }
    __syncthreads();
    int run = wsum[wid] + incl - sum;
    g_rowptr[t*4+0] = run; g_fill[t*4+0] = run; run += c0;
    g_rowptr[t*4+1] = run; g_fill[t*4+1] = run; run += c1;
    g_rowptr[t*4+2] = run; g_fill[t*4+2] = run; run += c2;
    g_rowptr[t*4+3] = run; g_fill[t*4+3] = run; run += c3;
    if (t == 1023) g_rowptr[NN] = run;
}

__global__ void k_scatter(const int* __restrict__ erow,
                          const int* __restrict__ ecol,
                          const float* __restrict__ eval) {
    int i = blockIdx.x * blockDim.x + threadIdx.x;
    if (i < NNZ_) {
        int r = erow[i];
        int pos = atomicAdd(&g_fill[r], 1);
        g_ccol[pos] = ecol[i];
        g_cval[pos] = eval[i];
    }
}

// ---------------------------------------------------------------------------
// 3) SPMM pass: x_k = (k==1) ? L x_0 : 2 L x_{k-1} - x_{k-2}  (fp16 storage)
// ---------------------------------------------------------------------------
__device__ __forceinline__ void acc_edge(float4& acc, float v, uint2 u) {
    float2 fa = __half22float2(*reinterpret_cast<__half2*>(&u.x));
    float2 fb = __half22float2(*reinterpret_cast<__half2*>(&u.y));
    acc.x = fmaf(v, fa.x, acc.x);
    acc.y = fmaf(v, fa.y, acc.y);
    acc.z = fmaf(v, fb.x, acc.z);
    acc.w = fmaf(v, fb.y, acc.w);
}

__global__ void __launch_bounds__(256) k_spmm(int k) {
    __shared__ int   sc[64];
    __shared__ float sv[64];
    int n = blockIdx.x;
    int t = threadIdx.x;
    int s = g_rowptr[n], e = g_rowptr[n+1];
    const __half* __restrict__ xin = g_xh[k-1];
    float4 acc = make_float4(0.f, 0.f, 0.f, 0.f);
    for (int base = s; base < e; base += 64) {
        int cnt = min(64, e - base);
        if (t < cnt) { sc[t] = g_ccol[base + t]; sv[t] = g_cval[base + t]; }
        __syncthreads();
        int i = 0;
        for (; i + 4 <= cnt; i += 4) {
            uint2 u0 = *reinterpret_cast<const uint2*>(xin + (size_t)sc[i+0]*ROWW + t*4);
            uint2 u1 = *reinterpret_cast<const uint2*>(xin + (size_t)sc[i+1]*ROWW + t*4);
            uint2 u2 = *reinterpret_cast<const uint2*>(xin + (size_t)sc[i+2]*ROWW + t*4);
            uint2 u3 = *reinterpret_cast<const uint2*>(xin + (size_t)sc[i+3]*ROWW + t*4);
            acc_edge(acc, sv[i+0], u0);
            acc_edge(acc, sv[i+1], u1);
            acc_edge(acc, sv[i+2], u2);
            acc_edge(acc, sv[i+3], u3);
        }
        for (; i < cnt; i++) {
            uint2 u = *reinterpret_cast<const uint2*>(xin + (size_t)sc[i]*ROWW + t*4);
            acc_edge(acc, sv[i], u);
        }
        __syncthreads();
    }
    float4 r = acc;
    if (k > 1) {
        uint2 pu = *reinterpret_cast<const uint2*>(&g_xh[k-2][(size_t)n*ROWW + t*4]);
        float2 pa = __half22float2(*reinterpret_cast<__half2*>(&pu.x));
        float2 pb = __half22float2(*reinterpret_cast<__half2*>(&pu.y));
        r.x = 2.f*acc.x - pa.x;
        r.y = 2.f*acc.y - pa.y;
        r.z = 2.f*acc.z - pb.x;
        r.w = 2.f*acc.w - pb.y;
    }
    __half2 h0 = __floats2half2_rn(r.x, r.y);
    __half2 h1 = __floats2half2_rn(r.z, r.w);
    uint2 hu;
    hu.x = *reinterpret_cast<unsigned*>(&h0);
    hu.y = *reinterpret_cast<unsigned*>(&h1);
    *reinterpret_cast<uint2*>(&g_xh[k][(size_t)n*ROWW + t*4]) = hu;
}

// ---------------------------------------------------------------------------
// 4) Tensor-core GEMM + bias + ReLU + maxpool(P=4)
//    Block = 2 pool groups: M=256 rows (8 nodes x 32 b), N=64, K=160.
//    8 warps, warp w owns node w. aS f-major [80][264], wS [160][72].
// ---------------------------------------------------------------------------
#define A_STRIDE 264   // halves; 528B = 33*16B (odd multiple of 16B -> conflict-free)
#define W_STRIDE 72    // halves; 144B = 9*16B
#define GEMM_SMEM 66560  // max(aS+wS = 42240+23040=65280, red = 256*64*4 = 65536) + pad

__device__ __forceinline__ void ldsm_x4_trans(unsigned& r0, unsigned& r1,
                                              unsigned& r2, unsigned& r3,
                                              unsigned addr) {
    asm volatile("ldmatrix.sync.aligned.m8n8.x4.trans.shared.b16 {%0,%1,%2,%3}, [%4];\n"
                 : "=r"(r0), "=r"(r1), "=r"(r2), "=r"(r3) : "r"(addr));
}

__device__ __forceinline__ void mma16816(float* d, unsigned a0, unsigned a1,
                                         unsigned a2, unsigned a3,
                                         unsigned b0, unsigned b1) {
    asm volatile("mma.sync.aligned.m16n8k16.row.col.f32.f16.f16.f32 "
                 "{%0,%1,%2,%3}, {%4,%5,%6,%7}, {%8,%9}, {%0,%1,%2,%3};\n"
                 : "+f"(d[0]), "+f"(d[1]), "+f"(d[2]), "+f"(d[3])
                 : "r"(a0), "r"(a1), "r"(a2), "r"(a3), "r"(b0), "r"(b1));
}

__global__ void __launch_bounds__(256) k_gemm(const float* __restrict__ W,
                                              const float* __restrict__ bias,
                                              float* __restrict__ out) {
    extern __shared__ __align__(16) char buf[];
    __half* aS = reinterpret_cast<__half*>(buf);                 // [80][A_STRIDE]
    __half* wS = reinterpret_cast<__half*>(buf + 80*A_STRIDE*2); // [160][W_STRIDE]
    float*  red = reinterpret_cast<float*>(buf);                 // [256][64] after sync

    int g  = blockIdx.x;          // 0..511
    int n0 = g * 8;               // 8 nodes = 2 pool groups
    int t  = threadIdx.x;
    int w  = t >> 5;              // warp = node 0..7
    int lane = t & 31;

    unsigned aS_base = (unsigned)__cvta_generic_to_shared(aS);
    unsigned wS_base = (unsigned)__cvta_generic_to_shared(wS);

    float acc[2][8][4];
    #pragma unroll
    for (int mt = 0; mt < 2; mt++)
        #pragma unroll
        for (int nt = 0; nt < 8; nt++)
            #pragma unroll
            for (int d = 0; d < 4; d++) acc[mt][nt][d] = 0.f;

    // stage W (fp32 -> fp16), once: 160*64 elems, float4 chunks, 256 threads
    #pragma unroll
    for (int it = 0; it < 10; it++) {
        int ch = it*256 + t;             // 0..2559
        int f  = ch >> 4;
        int o4 = (ch & 15) * 4;
        float4 wv = *reinterpret_cast<const float4*>(W + f*COUT + o4);
        __half2 h0 = __floats2half2_rn(wv.x, wv.y);
        __half2 h1 = __floats2half2_rn(wv.z, wv.w);
        uint2 hu;
        hu.x = *reinterpret_cast<unsigned*>(&h0);
        hu.y = *reinterpret_cast<unsigned*>(&h1);
        *reinterpret_cast<uint2*>(wS + f*W_STRIDE + o4) = hu;
    }

    for (int f0 = 0; f0 < NF; f0 += 80) {
        // stage A slice: 80 features x 256 rows, f-major
        #pragma unroll
        for (int it = 0; it < 10; it++) {
            int ch = it*256 + t;         // 0..2559
            int lf = ch >> 5;            // 0..79
            int rc = ch & 31;
            int p  = rc >> 2;            // 0..7
            int bq = rc & 3;             // b0/8
            int f  = f0 + lf;
            int c  = f / KDEG;
            int k  = f - KDEG*c;
            uint4 v = *reinterpret_cast<const uint4*>(
                &g_xh[k][(size_t)(n0 + p)*ROWW + c*32 + bq*8]);
            *reinterpret_cast<uint4*>(aS + lf*A_STRIDE + p*32 + bq*8) = v;
        }
        __syncthreads();

        #pragma unroll
        for (int kc = 0; kc < 5; kc++) {
            int lf0 = kc * 16;
            int fg  = f0 + lf0;
            int grp = lane >> 3, lrow = lane & 7;
            int a_f = lf0 + ((grp == 2 || grp == 3) ? 8 : 0) + lrow;
            int a_c = ((grp == 1 || grp == 3) ? 8 : 0);
            unsigned a0r, a1r, a2r, a3r, a4r, a5r, a6r, a7r;
            {
                unsigned addr0 = aS_base + (a_f*A_STRIDE + w*32 + 0*16 + a_c) * 2;
                ldsm_x4_trans(a0r, a1r, a2r, a3r, addr0);
                unsigned addr1 = aS_base + (a_f*A_STRIDE + w*32 + 1*16 + a_c) * 2;
                ldsm_x4_trans(a4r, a5r, a6r, a7r, addr1);
            }
            int b_f = fg + ((grp == 1 || grp == 3) ? 8 : 0) + lrow;
            int b_n = ((grp == 2 || grp == 3) ? 8 : 0);
            #pragma unroll
            for (int ntp = 0; ntp < 4; ntp++) {
                unsigned b0r, b1r, b2r, b3r;
                unsigned addr = wS_base + (b_f*W_STRIDE + ntp*16 + b_n) * 2;
                ldsm_x4_trans(b0r, b1r, b2r, b3r, addr);
                mma16816(acc[0][ntp*2+0], a0r, a1r, a2r, a3r, b0r, b1r);
                mma16816(acc[0][ntp*2+1], a0r, a1r, a2r, a3r, b2r, b3r);
                mma16816(acc[1][ntp*2+0], a4r, a5r, a6r, a7r, b0r, b1r);
                mma16816(acc[1][ntp*2+1], a4r, a5r, a6r, a7r, b2r, b3r);
            }
        }
        __syncthreads();
    }

    // write accumulators to red[row256][64]
    #pragma unroll
    for (int mt = 0; mt < 2; mt++) {
        int r1 = mt*16 + (lane >> 2);
        #pragma unroll
        for (int nt = 0; nt < 8; nt++) {
            int c = nt*8 + (lane & 3)*2;
            red[(w*32 + r1)*64 + c]     = acc[mt][nt][0];
            red[(w*32 + r1)*64 + c + 1] = acc[mt][nt][1];
            red[(w*32 + r1 + 8)*64 + c]     = acc[mt][nt][2];
            red[(w*32 + r1 + 8)*64 + c + 1] = acc[mt][nt][3];
        }
    }
    __syncthreads();

    // bias + relu + maxpool across p, 2 groups, write out[b][gout][o]
    #pragma unroll
    for (int it = 0; it < 16; it++) {
        int idx = it*256 + t;        // 0..4095
        int gq = idx >> 11;          // 0..1
        int r  = idx & 2047;
        int b  = r >> 6;
        int o  = r & 63;
        float bo = bias[o];
        float m = 0.f;               // relu floor
        #pragma unroll
        for (int p = 0; p < 4; p++)
            m = fmaxf(m, red[((gq*4 + p)*32 + b)*64 + o] + bo);
        out[(size_t)b*((NN/PP)*COUT) + (size_t)(g*2 + gq)*COUT + o] = m;
    }
}

// ---------------------------------------------------------------------------
extern "C" void kernel_launch(void* const* d_in, const int* in_sizes, int n_in,
                              void* d_out, int out_size) {
    const float* x        = (const float*)d_in[0];
    const float* edge_val = (const float*)d_in[1];
    const float* weight   = (const float*)d_in[2];
    const float* bias     = (const float*)d_in[3];
    const int*   edge_row = (const int*)d_in[4];
    const int*   edge_col = (const int*)d_in[5];
    float* out = (float*)d_out;

    cudaFuncSetAttribute(k_gemm, cudaFuncAttributeMaxDynamicSharedMemorySize,
                         GEMM_SMEM);

    k_tc<<<NN, dim3(32, 32)>>>(x, edge_row);
    k_scan<<<1, 1024>>>();
    k_scatter<<<(NNZ_ + 255)/256, 256>>>(edge_row, edge_col, edge_val);
    for (int k = 1; k < KDEG; k++)
        k_spmm<<<NN, 256>>>(k);
    k_gemm<<<NN/(PP*2), 256, GEMM_SMEM>>>(weight, bias, out);
}